// round 14
// baseline (speedup 1.0000x reference)
#include <cuda_runtime.h>
#include <stdint.h>

// GateLayer: x (4096,4096) f32, idx_l/idx_r (16384,) int, alpha (16384,3) f32,
// y (4096,16384) f32.
#define MDIM    4096
#define GMAX    16384
#define ROWS    4          // rows per tile (one 16-B quad per column)

// Static device scratch (no cudaMalloc allowed)
__device__ __align__(16) unsigned int g_off[GMAX];  // packed swizzled offsets
__device__ __align__(16) float2       g_cf[GMAX];

// ---------------------------------------------------------------------------
// Prep with fused int64/int32 detection. Every block samples the first 512
// 32-bit words of il/ir: OR of odd words is 0 iff idx is int64 (values < 4096
// -> high halves zero; if int32 those words are random indices, so the OR is
// nonzero w.o.p.). All blocks reach the same decision independently.
// Emits PACKED pre-swizzled smem quad byte offsets
//   P(c) = (c ^ ((c>>3)&7)) << 4   (max 65520, fits 16 bits)
//   g_off[g] = P(il) | P(ir) << 16
// and folded softmax coeffs: y = c_ab*ab + c_s*(a+b),
//   c_ab = w0-w1-2w2, c_s = w1+w2.
// ---------------------------------------------------------------------------
__global__ void prep_kernel(const unsigned int* __restrict__ il_raw,
                            const unsigned int* __restrict__ ir_raw,
                            const float* __restrict__ alpha, int G) {
    int t = threadIdx.x;
    unsigned int acc = 0;
    int i = t * 2 + 1;
    if (i < min(G, 512)) acc = il_raw[i] | ir_raw[i];
    int is64 = !__syncthreads_or(acc != 0u);

    int g = blockIdx.x * blockDim.x + t;
    if (g >= G) return;
    unsigned int il, ir;
    if (is64) { il = il_raw[2 * g]; ir = ir_raw[2 * g]; }
    else      { il = il_raw[g];     ir = ir_raw[g];     }
    unsigned int P = (il ^ ((il >> 3) & 7u)) << 4;
    unsigned int Q = (ir ^ ((ir >> 3) & 7u)) << 4;
    g_off[g] = P | (Q << 16);

    float a0 = alpha[3 * g + 0], a1 = alpha[3 * g + 1], a2 = alpha[3 * g + 2];
    float m  = fmaxf(a0, fmaxf(a1, a2));
    float e0 = expf(a0 - m), e1 = expf(a1 - m), e2 = expf(a2 - m);
    float inv = 1.0f / (e0 + e1 + e2);
    float w0 = e0 * inv, w1 = e1 * inv, w2 = e2 * inv;
    g_cf[g] = make_float2(w0 - w1 - 2.0f * w2, w1 + w2);
}

// ---------------------------------------------------------------------------
// Main kernel, 3 blocks/SM (regs <= 42 by construction: 1 g per thread keeps
// live state tiny; 48 warps/SM saturate the L1/LSU pipe that binds this
// kernel). SMEM holds 4 rows of x TRANSPOSED: column c is ONE 16-B quad
// (rows 0-3) at byte P(c) = (c ^ ((c>>3)&7)) << 4 (bijective; staging STS
// conflict-free: for each float4 component j, the 8 lanes of a phase cover
// all 8 bank slots). One LDS.128 gathers rows 0-3 of one column.
// Thread = 1 g x 4 rows = 4 outputs/iter:
//   2 LDS.128 + 4 STG.32 + 2 LDG  (offsets packed, no address ALU chain).
// Warp stores are dense 128-B rows; offset/cf loads are dense 128/256 B.
// ---------------------------------------------------------------------------
__global__ __launch_bounds__(512, 3)
void gate_kernel(const float* __restrict__ x, float* __restrict__ y, int G) {
    extern __shared__ float sm[];
    char* smb = (char*)sm;
    const int tid  = threadIdx.x;
    const int warp = tid >> 5, lane = tid & 31;
    const int row0 = blockIdx.x * ROWS;

    // ---- Stage: 4 rows, transposed + swizzled, conflict-free STS ----
    {
        const int r  = lane >> 3;              // 0..3
        const int cs = lane & 7;               // 0..7
        const float4* x4 = (const float4*)(x + (size_t)(row0 + r) * MDIM);
        #pragma unroll
        for (int i = 0; i < 8; i++) {
            int c4 = warp * 8 + cs + i * 128;  // float4 index 0..1023
            float4 v = x4[c4];
            int c0 = c4 * 4;
            #pragma unroll
            for (int j = 0; j < 4; j++) {
                int c = c0 + j;
                int P = ((c ^ ((c >> 3) & 7)) << 4) + r * 4;
                *(float*)(smb + P) = (&v.x)[j];
            }
        }
    }
    __syncthreads();

    float* yr0 = y + (size_t)(row0 + 0) * G;
    float* yr1 = y + (size_t)(row0 + 1) * G;
    float* yr2 = y + (size_t)(row0 + 2) * G;
    float* yr3 = y + (size_t)(row0 + 3) * G;

    // 1 g per thread; 512 threads cover 512 g per sweep; 32 sweeps cover G.
    #pragma unroll 2
    for (int gb = tid; gb < G; gb += 512) {
        unsigned int po = g_off[gb];
        float2 cf = g_cf[gb];

        float4 a = *(const float4*)(smb + (po & 0xFFFFu));
        float4 b = *(const float4*)(smb + (po >> 16));

        yr0[gb] = fmaf(cf.x, a.x * b.x, cf.y * (a.x + b.x));
        yr1[gb] = fmaf(cf.x, a.y * b.y, cf.y * (a.y + b.y));
        yr2[gb] = fmaf(cf.x, a.z * b.z, cf.y * (a.z + b.z));
        yr3[gb] = fmaf(cf.x, a.w * b.w, cf.y * (a.w + b.w));
    }
}

// ---------------------------------------------------------------------------
extern "C" void kernel_launch(void* const* d_in, const int* in_sizes, int n_in,
                              void* d_out, int out_size) {
    const float*        x     = (const float*)d_in[0];
    const unsigned int* il    = (const unsigned int*)d_in[1];
    const unsigned int* ir    = (const unsigned int*)d_in[2];
    const float*        alpha = (const float*)d_in[3];
    float*              y     = (float*)d_out;

    const int G = in_sizes[1];               // 16384
    const int B = in_sizes[0] / MDIM;        // 4096

    prep_kernel<<<(G + 255) / 256, 256>>>(il, ir, alpha, G);

    const int smemBytes = MDIM * 16;         // 65536 B (one quad per column)
    cudaFuncSetAttribute(gate_kernel, cudaFuncAttributeMaxDynamicSharedMemorySize,
                         smemBytes);

    gate_kernel<<<B / ROWS, 512, smemBytes>>>(x, y, G);
}

// round 15
// speedup vs baseline: 1.2615x; 1.2615x over previous
#include <cuda_runtime.h>
#include <stdint.h>

// GateLayer: x (4096,4096) f32, idx_l/idx_r (16384,) int, alpha (16384,3) f32,
// y (4096,16384) f32.
#define MDIM    4096
#define GMAX    16384
#define ROWS    4          // rows per tile (one 16-B quad per column)

// Static device scratch (no cudaMalloc allowed)
__device__ __align__(16) unsigned int g_off[GMAX];  // packed swizzled offsets
__device__ __align__(16) float2       g_cf[GMAX];

// ---------------------------------------------------------------------------
// Prep with fused int64/int32 detection. Every block samples the first 512
// 32-bit words of il/ir: OR of odd words is 0 iff idx is int64 (values < 4096
// -> high halves zero; if int32 those words are random indices, so the OR is
// nonzero w.o.p.). All blocks reach the same decision independently.
// Emits PACKED pre-swizzled smem quad byte offsets
//   P(c) = (c ^ ((c>>3)&7)) << 4   (max 65520, fits 16 bits)
//   g_off[g] = P(il) | P(ir) << 16
// and folded softmax coeffs: y = c_ab*ab + c_s*(a+b),
//   c_ab = w0-w1-2w2, c_s = w1+w2.
// ---------------------------------------------------------------------------
__global__ void prep_kernel(const unsigned int* __restrict__ il_raw,
                            const unsigned int* __restrict__ ir_raw,
                            const float* __restrict__ alpha, int G) {
    int t = threadIdx.x;
    unsigned int acc = 0;
    int i = t * 2 + 1;
    if (i < min(G, 512)) acc = il_raw[i] | ir_raw[i];
    int is64 = !__syncthreads_or(acc != 0u);

    int g = blockIdx.x * blockDim.x + t;
    if (g >= G) return;
    unsigned int il, ir;
    if (is64) { il = il_raw[2 * g]; ir = ir_raw[2 * g]; }
    else      { il = il_raw[g];     ir = ir_raw[g];     }
    unsigned int P = (il ^ ((il >> 3) & 7u)) << 4;
    unsigned int Q = (ir ^ ((ir >> 3) & 7u)) << 4;
    g_off[g] = P | (Q << 16);

    float a0 = alpha[3 * g + 0], a1 = alpha[3 * g + 1], a2 = alpha[3 * g + 2];
    float m  = fmaxf(a0, fmaxf(a1, a2));
    float e0 = expf(a0 - m), e1 = expf(a1 - m), e2 = expf(a2 - m);
    float inv = 1.0f / (e0 + e1 + e2);
    float w0 = e0 * inv, w1 = e1 * inv, w2 = e2 * inv;
    g_cf[g] = make_float2(w0 - w1 - 2.0f * w2, w1 + w2);
}

// ---------------------------------------------------------------------------
// Main kernel, 2 blocks/SM (staging of one block overlaps gather of the
// other). Each block stages its 4-row x tile ONCE and sweeps ALL of g.
// SMEM holds 4 rows of x TRANSPOSED: column c is ONE 16-B quad (rows 0-3) at
// byte P(c) = (c ^ ((c>>3)&7)) << 4   (bijective; staging STS conflict-free:
// for each float4 component j, the 8 lanes of a phase cover all 8 bank
// slots). One LDS.128 gathers rows 0-3 of one column.
// Thread = 4 g x 4 rows = 16 outputs/iter:
//   8 LDS.128 + 4 STG.128 + 3 LDG.128 = 15 LSU instructions
// (packed-offset LDG.128 covers all 4 g; unpack is 8 cheap ALU ops).
// ---------------------------------------------------------------------------
__global__ __launch_bounds__(512, 2)
void gate_kernel(const float* __restrict__ x, float* __restrict__ y, int G) {
    extern __shared__ float sm[];
    char* smb = (char*)sm;
    const int tid  = threadIdx.x;
    const int warp = tid >> 5, lane = tid & 31;
    const int row0 = blockIdx.x * ROWS;

    // ---- Stage: 4 rows, transposed + swizzled, conflict-free STS ----
    {
        const int r  = lane >> 3;              // 0..3
        const int cs = lane & 7;               // 0..7
        const float4* x4 = (const float4*)(x + (size_t)(row0 + r) * MDIM);
        #pragma unroll
        for (int i = 0; i < 8; i++) {
            int c4 = warp * 8 + cs + i * 128;  // float4 index 0..1023
            float4 v = x4[c4];
            int c0 = c4 * 4;
            #pragma unroll
            for (int j = 0; j < 4; j++) {
                int c = c0 + j;
                int P = ((c ^ ((c >> 3) & 7)) << 4) + r * 4;
                *(float*)(smb + P) = (&v.x)[j];
            }
        }
    }
    __syncthreads();

    float* yrow0 = y + (size_t)row0 * G;

    // 4 g per thread; 512 threads cover 2048 g per sweep; 8 sweeps cover G.
    #pragma unroll 1
    for (int gb = tid * 4; gb < G; gb += 2048) {
        uint4  po  = *(const uint4*)&g_off[gb];       // packed P|Q<<16, 4 g
        float4 cfA = *(const float4*)&g_cf[gb];       // (cab0,cs0,cab1,cs1)
        float4 cfB = *(const float4*)&g_cf[gb + 2];   // (cab2,cs2,cab3,cs3)

        float4 v0, v1, v2, v3;   // v{r} = outputs (g0,g1,g2,g3) at row r

        {   // g-pair 0 (g0, g1)
            float4 a0 = *(const float4*)(smb + (po.x & 0xFFFFu));
            float4 b0 = *(const float4*)(smb + (po.x >> 16));
            float4 a1 = *(const float4*)(smb + (po.y & 0xFFFFu));
            float4 b1 = *(const float4*)(smb + (po.y >> 16));
            v0.x = fmaf(cfA.x, a0.x * b0.x, cfA.y * (a0.x + b0.x));
            v1.x = fmaf(cfA.x, a0.y * b0.y, cfA.y * (a0.y + b0.y));
            v2.x = fmaf(cfA.x, a0.z * b0.z, cfA.y * (a0.z + b0.z));
            v3.x = fmaf(cfA.x, a0.w * b0.w, cfA.y * (a0.w + b0.w));
            v0.y = fmaf(cfA.z, a1.x * b1.x, cfA.w * (a1.x + b1.x));
            v1.y = fmaf(cfA.z, a1.y * b1.y, cfA.w * (a1.y + b1.y));
            v2.y = fmaf(cfA.z, a1.z * b1.z, cfA.w * (a1.z + b1.z));
            v3.y = fmaf(cfA.z, a1.w * b1.w, cfA.w * (a1.w + b1.w));
        }
        {   // g-pair 1 (g2, g3)
            float4 a2 = *(const float4*)(smb + (po.z & 0xFFFFu));
            float4 b2 = *(const float4*)(smb + (po.z >> 16));
            float4 a3 = *(const float4*)(smb + (po.w & 0xFFFFu));
            float4 b3 = *(const float4*)(smb + (po.w >> 16));
            v0.z = fmaf(cfB.x, a2.x * b2.x, cfB.y * (a2.x + b2.x));
            v1.z = fmaf(cfB.x, a2.y * b2.y, cfB.y * (a2.y + b2.y));
            v2.z = fmaf(cfB.x, a2.z * b2.z, cfB.y * (a2.z + b2.z));
            v3.z = fmaf(cfB.x, a2.w * b2.w, cfB.y * (a2.w + b2.w));
            v0.w = fmaf(cfB.z, a3.x * b3.x, cfB.w * (a3.x + b3.x));
            v1.w = fmaf(cfB.z, a3.y * b3.y, cfB.w * (a3.y + b3.y));
            v2.w = fmaf(cfB.z, a3.z * b3.z, cfB.w * (a3.z + b3.z));
            v3.w = fmaf(cfB.z, a3.w * b3.w, cfB.w * (a3.w + b3.w));
        }

        // 4 coalesced STG.128 (warp: 32 lanes x 16 B = one dense 512-B row)
        float* yp = yrow0 + gb;
        *(float4*)(yp + 0 * (size_t)G) = v0;
        *(float4*)(yp + 1 * (size_t)G) = v1;
        *(float4*)(yp + 2 * (size_t)G) = v2;
        *(float4*)(yp + 3 * (size_t)G) = v3;
    }
}

// ---------------------------------------------------------------------------
extern "C" void kernel_launch(void* const* d_in, const int* in_sizes, int n_in,
                              void* d_out, int out_size) {
    const float*        x     = (const float*)d_in[0];
    const unsigned int* il    = (const unsigned int*)d_in[1];
    const unsigned int* ir    = (const unsigned int*)d_in[2];
    const float*        alpha = (const float*)d_in[3];
    float*              y     = (float*)d_out;

    const int G = in_sizes[1];               // 16384
    const int B = in_sizes[0] / MDIM;        // 4096

    prep_kernel<<<(G + 255) / 256, 256>>>(il, ir, alpha, G);

    const int smemBytes = MDIM * 16;         // 65536 B (one quad per column)
    cudaFuncSetAttribute(gate_kernel, cudaFuncAttributeMaxDynamicSharedMemorySize,
                         smemBytes);

    gate_kernel<<<B / ROWS, 512, smemBytes>>>(x, y, G);
}

// round 16
// speedup vs baseline: 1.3299x; 1.0542x over previous
#include <cuda_runtime.h>
#include <stdint.h>

// GateLayer: x (4096,4096) f32, idx_l/idx_r (16384,) int, alpha (16384,3) f32,
// y (4096,16384) f32.
#define MDIM    4096
#define GMAX    16384
#define ROWS    4          // rows per tile (one 16-B quad per column)

// Static device scratch (no cudaMalloc allowed)
__device__ __align__(16) unsigned int g_off[GMAX];  // packed swizzled offsets
__device__ __align__(16) float2       g_cf[GMAX];

// ---------------------------------------------------------------------------
// Prep with fused int64/int32 detection. Every block samples the first 512
// 32-bit words of il/ir: OR of odd words is 0 iff idx is int64 (values < 4096
// -> high halves zero; if int32 those words are random indices, so the OR is
// nonzero w.o.p.). All blocks reach the same decision independently.
// Emits PACKED pre-swizzled smem quad byte offsets
//   P(c) = (c ^ ((c>>3)&7)) << 4   (max 65520, fits 16 bits)
//   g_off[g] = P(il) | P(ir) << 16
// and folded softmax coeffs: y = c_ab*ab + c_s*(a+b),
//   c_ab = w0-w1-2w2, c_s = w1+w2.
// ---------------------------------------------------------------------------
__global__ void prep_kernel(const unsigned int* __restrict__ il_raw,
                            const unsigned int* __restrict__ ir_raw,
                            const float* __restrict__ alpha, int G) {
    int t = threadIdx.x;
    unsigned int acc = 0;
    int i = t * 2 + 1;
    if (i < min(G, 512)) acc = il_raw[i] | ir_raw[i];
    int is64 = !__syncthreads_or(acc != 0u);

    int g = blockIdx.x * blockDim.x + t;
    if (g >= G) return;
    unsigned int il, ir;
    if (is64) { il = il_raw[2 * g]; ir = ir_raw[2 * g]; }
    else      { il = il_raw[g];     ir = ir_raw[g];     }
    unsigned int P = (il ^ ((il >> 3) & 7u)) << 4;
    unsigned int Q = (ir ^ ((ir >> 3) & 7u)) << 4;
    g_off[g] = P | (Q << 16);

    float a0 = alpha[3 * g + 0], a1 = alpha[3 * g + 1], a2 = alpha[3 * g + 2];
    float m  = fmaxf(a0, fmaxf(a1, a2));
    float e0 = expf(a0 - m), e1 = expf(a1 - m), e2 = expf(a2 - m);
    float inv = 1.0f / (e0 + e1 + e2);
    float w0 = e0 * inv, w1 = e1 * inv, w2 = e2 * inv;
    g_cf[g] = make_float2(w0 - w1 - 2.0f * w2, w1 + w2);
}

// ---------------------------------------------------------------------------
// Main kernel, 3 blocks/SM (2 g/thread keeps live state ~36 regs, under the
// 42-reg ceiling for 1536 thr/SM; extra occupancy soaks up the ~20% idle L1
// headroom measured at 2 blocks/SM while keeping >= 16 B per LSU instruction,
// the R14 lesson). SMEM holds 4 rows of x TRANSPOSED: column c is ONE 16-B
// quad (rows 0-3) at byte P(c) = (c ^ ((c>>3)&7)) << 4 (bijective; staging
// STS conflict-free: per float4 component j, the 8 lanes of a phase cover all
// 8 bank slots). One LDS.128 gathers rows 0-3 of one column.
// Thread = 2 g x 4 rows = 8 outputs/iter:
//   4 LDS.128 + 4 STG.64 + 2 LDG = 10 LSU instructions / 256 outputs-warp.
// Warp stores are dense 256-B rows; po/cf loads are dense 256/512 B.
// ---------------------------------------------------------------------------
__global__ __launch_bounds__(512, 3)
void gate_kernel(const float* __restrict__ x, float* __restrict__ y, int G) {
    extern __shared__ float sm[];
    char* smb = (char*)sm;
    const int tid  = threadIdx.x;
    const int warp = tid >> 5, lane = tid & 31;
    const int row0 = blockIdx.x * ROWS;

    // ---- Stage: 4 rows, transposed + swizzled, conflict-free STS ----
    {
        const int r  = lane >> 3;              // 0..3
        const int cs = lane & 7;               // 0..7
        const float4* x4 = (const float4*)(x + (size_t)(row0 + r) * MDIM);
        #pragma unroll
        for (int i = 0; i < 8; i++) {
            int c4 = warp * 8 + cs + i * 128;  // float4 index 0..1023
            float4 v = x4[c4];
            int c0 = c4 * 4;
            #pragma unroll
            for (int j = 0; j < 4; j++) {
                int c = c0 + j;
                int P = ((c ^ ((c >> 3) & 7)) << 4) + r * 4;
                *(float*)(smb + P) = (&v.x)[j];
            }
        }
    }
    __syncthreads();

    float* yrow0 = y + (size_t)row0 * G;

    // 2 g per thread; 512 threads cover 1024 g per sweep; 16 sweeps cover G.
    #pragma unroll 1
    for (int gb = tid * 2; gb < G; gb += 1024) {
        uint2  po = *(const uint2*)&g_off[gb];       // packed P|Q<<16, 2 g
        float4 cf = *(const float4*)&g_cf[gb];       // (cab0,cs0,cab1,cs1)

        float4 a0 = *(const float4*)(smb + (po.x & 0xFFFFu));
        float4 b0 = *(const float4*)(smb + (po.x >> 16));
        float4 a1 = *(const float4*)(smb + (po.y & 0xFFFFu));
        float4 b1 = *(const float4*)(smb + (po.y >> 16));

        float2 v0, v1, v2, v3;   // v{r} = outputs (g0,g1) at row r
        v0.x = fmaf(cf.x, a0.x * b0.x, cf.y * (a0.x + b0.x));
        v1.x = fmaf(cf.x, a0.y * b0.y, cf.y * (a0.y + b0.y));
        v2.x = fmaf(cf.x, a0.z * b0.z, cf.y * (a0.z + b0.z));
        v3.x = fmaf(cf.x, a0.w * b0.w, cf.y * (a0.w + b0.w));
        v0.y = fmaf(cf.z, a1.x * b1.x, cf.w * (a1.x + b1.x));
        v1.y = fmaf(cf.z, a1.y * b1.y, cf.w * (a1.y + b1.y));
        v2.y = fmaf(cf.z, a1.z * b1.z, cf.w * (a1.z + b1.z));
        v3.y = fmaf(cf.z, a1.w * b1.w, cf.w * (a1.w + b1.w));

        // 4 coalesced STG.64 (warp: 32 lanes x 8 B = one dense 256-B row)
        float* yp = yrow0 + gb;
        *(float2*)(yp + 0 * (size_t)G) = v0;
        *(float2*)(yp + 1 * (size_t)G) = v1;
        *(float2*)(yp + 2 * (size_t)G) = v2;
        *(float2*)(yp + 3 * (size_t)G) = v3;
    }
}

// ---------------------------------------------------------------------------
extern "C" void kernel_launch(void* const* d_in, const int* in_sizes, int n_in,
                              void* d_out, int out_size) {
    const float*        x     = (const float*)d_in[0];
    const unsigned int* il    = (const unsigned int*)d_in[1];
    const unsigned int* ir    = (const unsigned int*)d_in[2];
    const float*        alpha = (const float*)d_in[3];
    float*              y     = (float*)d_out;

    const int G = in_sizes[1];               // 16384
    const int B = in_sizes[0] / MDIM;        // 4096

    prep_kernel<<<(G + 255) / 256, 256>>>(il, ir, alpha, G);

    const int smemBytes = MDIM * 16;         // 65536 B (one quad per column)
    cudaFuncSetAttribute(gate_kernel, cudaFuncAttributeMaxDynamicSharedMemorySize,
                         smemBytes);

    gate_kernel<<<B / ROWS, 512, smemBytes>>>(x, y, G);
}

// round 17
// speedup vs baseline: 1.3801x; 1.0378x over previous
#include <cuda_runtime.h>
#include <stdint.h>

// GateLayer: x (4096,4096) f32, idx_l/idx_r (16384,) int, alpha (16384,3) f32,
// y (4096,16384) f32.
#define MDIM    4096
#define GMAX    16384
#define ROWS    4          // rows per tile (one 16-B quad per column)

// Static device scratch (no cudaMalloc allowed)
__device__ __align__(16) unsigned int g_off[GMAX];  // packed swizzled offsets
__device__ __align__(16) float2       g_cf[GMAX];

// ---------------------------------------------------------------------------
// Prep with fused int64/int32 detection AND fused conflict balancing.
//
// Detection: every block samples the first 512 32-bit words of il/ir: OR of
// odd words is 0 iff idx is int64 (values < 4096 -> high halves zero).
//
// Offsets: P(c) = (c ^ ((c>>3)&7)) << 4 (fits 16 bits), packed
//   g_off[g] = P_a | P_b << 16  where (a,b) is a per-g ORIENTATION of
// (il,ir) chosen to minimize LDS bank conflicts. Legal because the gate is
// symmetric: y = c_ab*ab + c_s*(a+b).
//
// Conflict model (matches gate_kernel's static access pattern): for warp w,
// quarter-warp phase m, sweep k, the 'a'-gather instruction reads the quads
// of the EVEN g's of the aligned 16-window [64w+16m+1024k, +16), and the
// 'b'-instruction the same g's other operand; odd g's form the second
// instruction pair. A quad at byte P lives in bank-slot (P>>4)&7; a phase's
// wavefronts = max slot multiplicity. Greedy 2-choice balancing of the 8
// (slot_a, slot_b) pairs into two 8-bin histograms drops E[max] ~2.5 -> ~1.8.
//
// Coeffs: c_ab = w0-w1-2w2, c_s = w1+w2 from softmax(alpha).
// ---------------------------------------------------------------------------
__global__ void prep_kernel(const unsigned int* __restrict__ il_raw,
                            const unsigned int* __restrict__ ir_raw,
                            const float* __restrict__ alpha, int G) {
    __shared__ unsigned short sP[256], sQ[256];
    int t = threadIdx.x;
    unsigned int acc = 0;
    int i = t * 2 + 1;
    if (i < min(G, 512)) acc = il_raw[i] | ir_raw[i];
    int is64 = !__syncthreads_or(acc != 0u);

    int g = blockIdx.x * blockDim.x + t;   // blockDim = 256, grid = G/256
    unsigned int P = 0, Q = 0;
    if (g < G) {
        unsigned int il, ir;
        if (is64) { il = il_raw[2 * g]; ir = ir_raw[2 * g]; }
        else      { il = il_raw[g];     ir = ir_raw[g];     }
        P = (il ^ ((il >> 3) & 7u)) << 4;
        Q = (ir ^ ((ir >> 3) & 7u)) << 4;

        float a0 = alpha[3 * g + 0], a1 = alpha[3 * g + 1], a2 = alpha[3 * g + 2];
        float m  = fmaxf(a0, fmaxf(a1, a2));
        float e0 = expf(a0 - m), e1 = expf(a1 - m), e2 = expf(a2 - m);
        float inv = 1.0f / (e0 + e1 + e2);
        float w0 = e0 * inv, w1 = e1 * inv, w2 = e2 * inv;
        g_cf[g] = make_float2(w0 - w1 - 2.0f * w2, w1 + w2);
    }
    sP[t] = (unsigned short)P;
    sQ[t] = (unsigned short)Q;
    __syncthreads();

    // 32 threads: one per (16-g window, parity) group of 8 pairs.
    if (t < 32) {
        int win = t >> 1, par = t & 1;         // 16 windows per block
        int lbase = win * 16 + par;
        unsigned long long hA = 0ull, hB = 0ull;   // 8 byte-bins each
        int gbase = blockIdx.x * 256 + lbase;
        #pragma unroll 1
        for (int j = 0; j < 8; j++) {
            int li = lbase + 2 * j;
            unsigned int p = sP[li], q = sQ[li];
            int sa = (p >> 4) & 7, sb = (q >> 4) & 7;
            int cN = max((int)((hA >> (sa * 8)) & 255),
                         (int)((hB >> (sb * 8)) & 255));
            int cS = max((int)((hA >> (sb * 8)) & 255),
                         (int)((hB >> (sa * 8)) & 255));
            if (cS < cN) {                     // swap orientation (symmetric)
                unsigned int tp = p; p = q; q = tp;
                int ts = sa; sa = sb; sb = ts;
            }
            hA += 1ull << (sa * 8);
            hB += 1ull << (sb * 8);
            int gg = gbase + 2 * j;
            if (gg < G) g_off[gg] = p | (q << 16);
        }
    }
}

// ---------------------------------------------------------------------------
// Main kernel, 3 blocks/SM (2 g/thread, ~40 regs; 48 warps/SM). SMEM holds 4
// rows of x TRANSPOSED: column c is ONE 16-B quad (rows 0-3) at byte
// P(c) = (c ^ ((c>>3)&7)) << 4 (bijective; staging STS conflict-free: per
// float4 component j, the 8 lanes of a phase cover all 8 bank slots).
// One LDS.128 gathers rows 0-3 of one column. Thread = 2 g x 4 rows = 8
// outputs/iter: 4 LDS.128 + 4 STG.64 + 2 LDG. (Identical to R16 gate -- the
// only change this round is prep-side conflict balancing of g_off.)
// ---------------------------------------------------------------------------
__global__ __launch_bounds__(512, 3)
void gate_kernel(const float* __restrict__ x, float* __restrict__ y, int G) {
    extern __shared__ float sm[];
    char* smb = (char*)sm;
    const int tid  = threadIdx.x;
    const int warp = tid >> 5, lane = tid & 31;
    const int row0 = blockIdx.x * ROWS;

    // ---- Stage: 4 rows, transposed + swizzled, conflict-free STS ----
    {
        const int r  = lane >> 3;              // 0..3
        const int cs = lane & 7;               // 0..7
        const float4* x4 = (const float4*)(x + (size_t)(row0 + r) * MDIM);
        #pragma unroll
        for (int i = 0; i < 8; i++) {
            int c4 = warp * 8 + cs + i * 128;  // float4 index 0..1023
            float4 v = x4[c4];
            int c0 = c4 * 4;
            #pragma unroll
            for (int j = 0; j < 4; j++) {
                int c = c0 + j;
                int P = ((c ^ ((c >> 3) & 7)) << 4) + r * 4;
                *(float*)(smb + P) = (&v.x)[j];
            }
        }
    }
    __syncthreads();

    float* yrow0 = y + (size_t)row0 * G;

    // 2 g per thread; 512 threads cover 1024 g per sweep; 16 sweeps cover G.
    #pragma unroll 1
    for (int gb = tid * 2; gb < G; gb += 1024) {
        uint2  po = *(const uint2*)&g_off[gb];       // packed P|Q<<16, 2 g
        float4 cf = *(const float4*)&g_cf[gb];       // (cab0,cs0,cab1,cs1)

        float4 a0 = *(const float4*)(smb + (po.x & 0xFFFFu));
        float4 b0 = *(const float4*)(smb + (po.x >> 16));
        float4 a1 = *(const float4*)(smb + (po.y & 0xFFFFu));
        float4 b1 = *(const float4*)(smb + (po.y >> 16));

        float2 v0, v1, v2, v3;   // v{r} = outputs (g0,g1) at row r
        v0.x = fmaf(cf.x, a0.x * b0.x, cf.y * (a0.x + b0.x));
        v1.x = fmaf(cf.x, a0.y * b0.y, cf.y * (a0.y + b0.y));
        v2.x = fmaf(cf.x, a0.z * b0.z, cf.y * (a0.z + b0.z));
        v3.x = fmaf(cf.x, a0.w * b0.w, cf.y * (a0.w + b0.w));
        v0.y = fmaf(cf.z, a1.x * b1.x, cf.w * (a1.x + b1.x));
        v1.y = fmaf(cf.z, a1.y * b1.y, cf.w * (a1.y + b1.y));
        v2.y = fmaf(cf.z, a1.z * b1.z, cf.w * (a1.z + b1.z));
        v3.y = fmaf(cf.z, a1.w * b1.w, cf.w * (a1.w + b1.w));

        // 4 coalesced STG.64 (warp: 32 lanes x 8 B = one dense 256-B row)
        float* yp = yrow0 + gb;
        *(float2*)(yp + 0 * (size_t)G) = v0;
        *(float2*)(yp + 1 * (size_t)G) = v1;
        *(float2*)(yp + 2 * (size_t)G) = v2;
        *(float2*)(yp + 3 * (size_t)G) = v3;
    }
}

// ---------------------------------------------------------------------------
extern "C" void kernel_launch(void* const* d_in, const int* in_sizes, int n_in,
                              void* d_out, int out_size) {
    const float*        x     = (const float*)d_in[0];
    const unsigned int* il    = (const unsigned int*)d_in[1];
    const unsigned int* ir    = (const unsigned int*)d_in[2];
    const float*        alpha = (const float*)d_in[3];
    float*              y     = (float*)d_out;

    const int G = in_sizes[1];               // 16384
    const int B = in_sizes[0] / MDIM;        // 4096

    prep_kernel<<<(G + 255) / 256, 256>>>(il, ir, alpha, G);

    const int smemBytes = MDIM * 16;         // 65536 B (one quad per column)
    cudaFuncSetAttribute(gate_kernel, cudaFuncAttributeMaxDynamicSharedMemorySize,
                         smemBytes);

    gate_kernel<<<B / ROWS, 512, smemBytes>>>(x, y, G);
}